// round 10
// baseline (speedup 1.0000x reference)
#include <cuda_runtime.h>
#include <math_constants.h>

// RightPool: out[b,c,h,w] = max(x[b,c,h,0..w]) — inclusive cummax along last
// axis, W = 128, fp32. Tensor (8,256,128,128) -> 262,144 rows of 128 floats.
//
// FINAL (locked R8 config — best measured: 36.61us kernel, 71.1% DRAM):
//  - 256-bit vector ld/st (ld/st.global.v8.b32): half-warp per row, lane h
//    owns elements [8h, 8h+8) — one 32B access per lane, rows fully dense.
//  - 2 front-batched LDG.256 per warp (4 rows/warp) for load-level ILP.
//  - Width-16 shfl_up inclusive max-scan (4 steps) of per-lane totals.
//  - 128-thread blocks, grid 16384: occ ~78%, finest wave granularity.
//  - Plain cached loads + writeback stores (measured best vs .cs/.nc).
// Session evidence: bench pinned at 45.06us across 7 structural variants ->
// compulsory-traffic DRAM ceiling (~5.95 TB/s effective 1:1 R/W stream).

static constexpr int W = 128;            // row length (elements)
static constexpr int PAIRS = 2;          // row-pairs per warp
static constexpr int ROWS_PER_WARP = 2 * PAIRS;
static constexpr int WARPS_PER_BLOCK = 4;
static constexpr int THREADS = WARPS_PER_BLOCK * 32;   // 128
static constexpr int ROWS_PER_BLOCK = WARPS_PER_BLOCK * ROWS_PER_WARP;

__device__ __forceinline__ void ldg256(const char* p, float a[8]) {
    asm volatile(
        "ld.global.v8.b32 {%0,%1,%2,%3,%4,%5,%6,%7}, [%8];"
        : "=f"(a[0]), "=f"(a[1]), "=f"(a[2]), "=f"(a[3]),
          "=f"(a[4]), "=f"(a[5]), "=f"(a[6]), "=f"(a[7])
        : "l"(p));
}

__device__ __forceinline__ void stg256(char* p, const float a[8]) {
    asm volatile(
        "st.global.v8.b32 [%8], {%0,%1,%2,%3,%4,%5,%6,%7};"
        :: "f"(a[0]), "f"(a[1]), "f"(a[2]), "f"(a[3]),
           "f"(a[4]), "f"(a[5]), "f"(a[6]), "f"(a[7]),
           "l"(p)
        : "memory");
}

__global__ __launch_bounds__(THREADS)
void rightpool_kernel(const float* __restrict__ x,
                      float* __restrict__ out,
                      int num_rows) {
    const int lane = threadIdx.x & 31;
    const int half = lane >> 4;          // which row of the pair
    const int h    = lane & 15;          // position within the row (16 lanes)
    const int warp = blockIdx.x * WARPS_PER_BLOCK + (threadIdx.x >> 5);
    const int row0 = warp * ROWS_PER_WARP;
    if (row0 >= num_rows) return;

    // 32-bit BYTE offsets (tensor is 128 MiB; offsets < 2^31).
    const unsigned tbyte = (unsigned)(row0 + half) * (W * 4) + (unsigned)h * 32;
    const char* xb = reinterpret_cast<const char*>(x) + tbyte;
    char*       ob = reinterpret_cast<char*>(out) + tbyte;
    constexpr unsigned PAIR_STRIDE = 2u * W * 4u;   // 1024 bytes

    // ---- Front-batched loads: PAIRS independent LDG.256 ----
    float a[PAIRS][8];
    #pragma unroll
    for (int p = 0; p < PAIRS; p++)
        ldg256(xb + p * PAIR_STRIDE, a[p]);

    // In-place local inclusive prefix max over the 8 owned elements.
    #pragma unroll
    for (int p = 0; p < PAIRS; p++)
        #pragma unroll
        for (int i = 1; i < 8; i++)
            a[p][i] = fmaxf(a[p][i - 1], a[p][i]);

    // Width-16 inclusive max-scan of segment totals across the half-warp.
    // shfl_up(width=16) returns own value when h < ofs; fmax(s,s)=s.
    float s[PAIRS];
    #pragma unroll
    for (int p = 0; p < PAIRS; p++) s[p] = a[p][7];

    #pragma unroll
    for (int ofs = 1; ofs < 16; ofs <<= 1) {
        float n[PAIRS];
        #pragma unroll
        for (int p = 0; p < PAIRS; p++)
            n[p] = __shfl_up_sync(0xFFFFFFFFu, s[p], ofs, 16);
        #pragma unroll
        for (int p = 0; p < PAIRS; p++) s[p] = fmaxf(s[p], n[p]);
    }

    // Exclusive prefix per segment, combine, 256-bit store.
    #pragma unroll
    for (int p = 0; p < PAIRS; p++) {
        float e = __shfl_up_sync(0xFFFFFFFFu, s[p], 1, 16);
        if (h == 0) e = -CUDART_INF_F;
        float o[8];
        #pragma unroll
        for (int i = 0; i < 8; i++) o[i] = fmaxf(e, a[p][i]);
        stg256(ob + p * PAIR_STRIDE, o);
    }
}

// Tail kernel: one warp per leftover row (unused for the bench shape).
__global__ __launch_bounds__(256)
void rightpool_tail_kernel(const float* __restrict__ x,
                           float* __restrict__ out,
                           int first_row, int num_rows) {
    const int lane = threadIdx.x & 31;
    const int row  = first_row + blockIdx.x * 8 + (threadIdx.x >> 5);
    if (row >= num_rows) return;
    const size_t base = (size_t)row * W + (size_t)lane * 4;
    float4 v = *reinterpret_cast<const float4*>(x + base);
    v.y = fmaxf(v.x, v.y); v.z = fmaxf(v.y, v.z); v.w = fmaxf(v.z, v.w);
    float s = v.w;
    #pragma unroll
    for (int ofs = 1; ofs < 32; ofs <<= 1)
        s = fmaxf(s, __shfl_up_sync(0xFFFFFFFFu, s, ofs));
    float e = __shfl_up_sync(0xFFFFFFFFu, s, 1);
    if (lane == 0) e = -CUDART_INF_F;
    float4 o = {fmaxf(e, v.x), fmaxf(e, v.y), fmaxf(e, v.z), fmaxf(e, v.w)};
    *reinterpret_cast<float4*>(out + base) = o;
}

extern "C" void kernel_launch(void* const* d_in, const int* in_sizes, int n_in,
                              void* d_out, int out_size) {
    const float* x = (const float*)d_in[0];
    float* out = (float*)d_out;
    const int n = in_sizes[0];
    const int num_rows = n / W;

    const int full_rows = (num_rows / ROWS_PER_WARP) * ROWS_PER_WARP;
    const int blocks = (full_rows + ROWS_PER_BLOCK - 1) / ROWS_PER_BLOCK;
    if (blocks > 0)
        rightpool_kernel<<<blocks, THREADS>>>(x, out, full_rows);

    const int tail_rows = num_rows - full_rows;
    if (tail_rows > 0) {
        const int tail_blocks = (tail_rows + 7) / 8;
        rightpool_tail_kernel<<<tail_blocks, 256>>>(x, out, full_rows, num_rows);
    }
}

// round 11
// speedup vs baseline: 1.0014x; 1.0014x over previous
#include <cuda_runtime.h>
#include <math_constants.h>

// RightPool: out[b,c,h,w] = max(x[b,c,h,0..w]) — inclusive cummax along last
// axis, W = 128, fp32. Tensor (8,256,128,128) -> 262,144 rows of 128 floats.
//
// R8 winning geometry (36.61us kernel best) + ONE isolated delta:
// streaming stores (st.global.cs.v8.b32). Rationale: steady-state replay
// cost includes draining ~128MB of dirty output from L2 before the next
// replay re-reads x; evict-first stores queue that writeback eagerly,
// overlapping the drain with kernel execution instead of deferring it to
// demand-eviction by the next replay's read stream. (.cs stores were only
// ever tested confounded with the R3 occupancy collapse.)

static constexpr int W = 128;            // row length (elements)
static constexpr int PAIRS = 2;          // row-pairs per warp
static constexpr int ROWS_PER_WARP = 2 * PAIRS;
static constexpr int WARPS_PER_BLOCK = 4;
static constexpr int THREADS = WARPS_PER_BLOCK * 32;   // 128
static constexpr int ROWS_PER_BLOCK = WARPS_PER_BLOCK * ROWS_PER_WARP;

__device__ __forceinline__ void ldg256(const char* p, float a[8]) {
    asm volatile(
        "ld.global.v8.b32 {%0,%1,%2,%3,%4,%5,%6,%7}, [%8];"
        : "=f"(a[0]), "=f"(a[1]), "=f"(a[2]), "=f"(a[3]),
          "=f"(a[4]), "=f"(a[5]), "=f"(a[6]), "=f"(a[7])
        : "l"(p));
}

__device__ __forceinline__ void stg256cs(char* p, const float a[8]) {
    asm volatile(
        "st.global.cs.v8.b32 [%8], {%0,%1,%2,%3,%4,%5,%6,%7};"
        :: "f"(a[0]), "f"(a[1]), "f"(a[2]), "f"(a[3]),
           "f"(a[4]), "f"(a[5]), "f"(a[6]), "f"(a[7]),
           "l"(p)
        : "memory");
}

__global__ __launch_bounds__(THREADS)
void rightpool_kernel(const float* __restrict__ x,
                      float* __restrict__ out,
                      int num_rows) {
    const int lane = threadIdx.x & 31;
    const int half = lane >> 4;          // which row of the pair
    const int h    = lane & 15;          // position within the row (16 lanes)
    const int warp = blockIdx.x * WARPS_PER_BLOCK + (threadIdx.x >> 5);
    const int row0 = warp * ROWS_PER_WARP;
    if (row0 >= num_rows) return;

    // 32-bit BYTE offsets (tensor is 128 MiB; offsets < 2^31).
    const unsigned tbyte = (unsigned)(row0 + half) * (W * 4) + (unsigned)h * 32;
    const char* xb = reinterpret_cast<const char*>(x) + tbyte;
    char*       ob = reinterpret_cast<char*>(out) + tbyte;
    constexpr unsigned PAIR_STRIDE = 2u * W * 4u;   // 1024 bytes

    // ---- Front-batched loads: PAIRS independent LDG.256 ----
    float a[PAIRS][8];
    #pragma unroll
    for (int p = 0; p < PAIRS; p++)
        ldg256(xb + p * PAIR_STRIDE, a[p]);

    // In-place local inclusive prefix max over the 8 owned elements.
    #pragma unroll
    for (int p = 0; p < PAIRS; p++)
        #pragma unroll
        for (int i = 1; i < 8; i++)
            a[p][i] = fmaxf(a[p][i - 1], a[p][i]);

    // Width-16 inclusive max-scan of segment totals across the half-warp.
    // shfl_up(width=16) returns own value when h < ofs; fmax(s,s)=s.
    float s[PAIRS];
    #pragma unroll
    for (int p = 0; p < PAIRS; p++) s[p] = a[p][7];

    #pragma unroll
    for (int ofs = 1; ofs < 16; ofs <<= 1) {
        float n[PAIRS];
        #pragma unroll
        for (int p = 0; p < PAIRS; p++)
            n[p] = __shfl_up_sync(0xFFFFFFFFu, s[p], ofs, 16);
        #pragma unroll
        for (int p = 0; p < PAIRS; p++) s[p] = fmaxf(s[p], n[p]);
    }

    // Exclusive prefix per segment, combine, 256-bit streaming store.
    #pragma unroll
    for (int p = 0; p < PAIRS; p++) {
        float e = __shfl_up_sync(0xFFFFFFFFu, s[p], 1, 16);
        if (h == 0) e = -CUDART_INF_F;
        float o[8];
        #pragma unroll
        for (int i = 0; i < 8; i++) o[i] = fmaxf(e, a[p][i]);
        stg256cs(ob + p * PAIR_STRIDE, o);
    }
}

// Tail kernel: one warp per leftover row (unused for the bench shape).
__global__ __launch_bounds__(256)
void rightpool_tail_kernel(const float* __restrict__ x,
                           float* __restrict__ out,
                           int first_row, int num_rows) {
    const int lane = threadIdx.x & 31;
    const int row  = first_row + blockIdx.x * 8 + (threadIdx.x >> 5);
    if (row >= num_rows) return;
    const size_t base = (size_t)row * W + (size_t)lane * 4;
    float4 v = *reinterpret_cast<const float4*>(x + base);
    v.y = fmaxf(v.x, v.y); v.z = fmaxf(v.y, v.z); v.w = fmaxf(v.z, v.w);
    float s = v.w;
    #pragma unroll
    for (int ofs = 1; ofs < 32; ofs <<= 1)
        s = fmaxf(s, __shfl_up_sync(0xFFFFFFFFu, s, ofs));
    float e = __shfl_up_sync(0xFFFFFFFFu, s, 1);
    if (lane == 0) e = -CUDART_INF_F;
    float4 o = {fmaxf(e, v.x), fmaxf(e, v.y), fmaxf(e, v.z), fmaxf(e, v.w)};
    *reinterpret_cast<float4*>(out + base) = o;
}

extern "C" void kernel_launch(void* const* d_in, const int* in_sizes, int n_in,
                              void* d_out, int out_size) {
    const float* x = (const float*)d_in[0];
    float* out = (float*)d_out;
    const int n = in_sizes[0];
    const int num_rows = n / W;

    const int full_rows = (num_rows / ROWS_PER_WARP) * ROWS_PER_WARP;
    const int blocks = (full_rows + ROWS_PER_BLOCK - 1) / ROWS_PER_BLOCK;
    if (blocks > 0)
        rightpool_kernel<<<blocks, THREADS>>>(x, out, full_rows);

    const int tail_rows = num_rows - full_rows;
    if (tail_rows > 0) {
        const int tail_blocks = (tail_rows + 7) / 8;
        rightpool_tail_kernel<<<tail_blocks, 256>>>(x, out, full_rows, num_rows);
    }
}